// round 1
// baseline (speedup 1.0000x reference)
#include <cuda_runtime.h>
#include <cuda_bf16.h>

#define HIDDEN 2048
#define SEQ    2048
#define BATCH  2
#define NHEADS 16
#define HDIM   128

typedef unsigned long long ull;

// ---------- f32x2 packed-math helpers (sm_100+/sm_103a) ----------
__device__ __forceinline__ ull fpack2(float lo, float hi) {
    ull r; asm("mov.b64 %0, {%1,%2};" : "=l"(r) : "f"(lo), "f"(hi)); return r;
}
__device__ __forceinline__ ull fdup2(float v) { return fpack2(v, v); }
__device__ __forceinline__ float2 funpack2(ull v) {
    float2 r; asm("mov.b64 {%0,%1}, %2;" : "=f"(r.x), "=f"(r.y) : "l"(v)); return r;
}
__device__ __forceinline__ ull ffma2(ull a, ull b, ull c) {
    ull d; asm("fma.rn.f32x2 %0, %1, %2, %3;" : "=l"(d) : "l"(a), "l"(b), "l"(c)); return d;
}
__device__ __forceinline__ ull fmul2_(ull a, ull b) {
    ull d; asm("mul.rn.f32x2 %0, %1, %2;" : "=l"(d) : "l"(a), "l"(b)); return d;
}

// ---------- scratch (no cudaMalloc allowed) ----------
__device__ float g_Q[BATCH * SEQ * HIDDEN];
__device__ float g_K[BATCH * SEQ * HIDDEN];
__device__ float g_V[BATCH * SEQ * HIDDEN];
__device__ float g_O[BATCH * SEQ * HIDDEN];

// =====================================================================
// SGEMM: C[M,N] = A[M,K] @ B[N,K]^T   (both row-major, K-contiguous)
// 128x128 block tile, BK=8, 256 threads, 8x8 per thread.
// f32x2 accumulation: pairs over adjacent rows (ld.shared.b64 from
// k-major A tile), B value duplicated. Strided col ownership tx+16j.
// =====================================================================
__global__ __launch_bounds__(256, 2)
void sgemm_nt(const float* __restrict__ A, const float* __restrict__ B,
              float* __restrict__ C, int M, int N, int K)
{
    __shared__ __align__(16) float As[2][8][128];
    __shared__ __align__(16) float Bs[2][8][128];

    const int tid = threadIdx.x;
    const int tx  = tid & 15;
    const int ty  = tid >> 4;
    const int lr  = tid >> 1;            // 0..127
    const int lc  = (tid & 1) * 4;       // 0 or 4
    const size_t brow = (size_t)blockIdx.y * 128;
    const size_t bcol = (size_t)blockIdx.x * 128;

    const float* Ag = A + (brow + lr) * (size_t)K + lc;
    const float* Bg = B + (bcol + lr) * (size_t)K + lc;

    ull acc[4][8];
#pragma unroll
    for (int i = 0; i < 4; ++i)
#pragma unroll
        for (int j = 0; j < 8; ++j) acc[i][j] = 0ull;

    float4 a4 = *(const float4*)Ag;
    float4 b4 = *(const float4*)Bg;
    As[0][lc + 0][lr] = a4.x; As[0][lc + 1][lr] = a4.y;
    As[0][lc + 2][lr] = a4.z; As[0][lc + 3][lr] = a4.w;
    Bs[0][lc + 0][lr] = b4.x; Bs[0][lc + 1][lr] = b4.y;
    Bs[0][lc + 2][lr] = b4.z; Bs[0][lc + 3][lr] = b4.w;
    __syncthreads();

    const int nk = K >> 3;
    int buf = 0;
    for (int t = 0; t < nk; ++t) {
        if (t + 1 < nk) {
            a4 = *(const float4*)(Ag + (size_t)(t + 1) * 8);
            b4 = *(const float4*)(Bg + (size_t)(t + 1) * 8);
        }
#pragma unroll
        for (int kk = 0; kk < 8; ++kk) {
            ull a2[4];
#pragma unroll
            for (int i = 0; i < 4; ++i)
                a2[i] = *(const ull*)&As[buf][kk][ty * 8 + 2 * i];
#pragma unroll
            for (int j = 0; j < 8; ++j) {
                ull bd = fdup2(Bs[buf][kk][tx + 16 * j]);
#pragma unroll
                for (int i = 0; i < 4; ++i)
                    acc[i][j] = ffma2(a2[i], bd, acc[i][j]);
            }
        }
        if (t + 1 < nk) {
            buf ^= 1;
            As[buf][lc + 0][lr] = a4.x; As[buf][lc + 1][lr] = a4.y;
            As[buf][lc + 2][lr] = a4.z; As[buf][lc + 3][lr] = a4.w;
            Bs[buf][lc + 0][lr] = b4.x; Bs[buf][lc + 1][lr] = b4.y;
            Bs[buf][lc + 2][lr] = b4.z; Bs[buf][lc + 3][lr] = b4.w;
            __syncthreads();
        }
    }

#pragma unroll
    for (int i = 0; i < 4; ++i) {
        size_t r0 = (brow + (size_t)ty * 8 + 2 * i) * (size_t)N + bcol;
#pragma unroll
        for (int j = 0; j < 8; ++j) {
            float2 f = funpack2(acc[i][j]);
            C[r0 + tx + 16 * j]              = f.x;
            C[r0 + (size_t)N + tx + 16 * j]  = f.y;
        }
    }
}

// =====================================================================
// Flash attention (non-causal), fp32, f32x2 packed inner loops.
// Per CTA: one (b, h, 64-row q tile). 256 threads = 16x16.
// Thread owns score rows ty*4..+3, score cols {tx+16j}, O cols {tx+16j}.
// smem (dynamic): Qs[64][128] | Kt[64][130] | Vt[128][66] | Ps[64][80]
// =====================================================================
#define ATTN_SMEM_FLOATS (8192 + 8320 + 8448 + 5120)
#define ATTN_SMEM_BYTES  (ATTN_SMEM_FLOATS * 4)

__global__ __launch_bounds__(256, 1)
void attn_kernel(const float* __restrict__ Q, const float* __restrict__ K,
                 const float* __restrict__ V, float* __restrict__ O)
{
    extern __shared__ __align__(16) float sm[];
    float* Qs = sm;                 // [64][128]
    float* Kt = sm + 8192;          // [64][130]   (kv-major, d contiguous)
    float* Vt = sm + 16512;         // [128][66]   (d-major, kv contiguous)
    float* Ps = sm + 24960;         // [64][80]

    const int tid = threadIdx.x;
    const int tx  = tid & 15;
    const int ty  = tid >> 4;
    const int b   = blockIdx.x >> 4;
    const int h   = blockIdx.x & 15;
    const int qt  = blockIdx.y;

    const float scale = 0.08838834764831843f;   // 1/sqrt(128)
    const size_t base = ((size_t)b * SEQ) * HIDDEN + (size_t)h * HDIM;

    // ---- load Q tile (scaled) ----
#pragma unroll
    for (int it = 0; it < 8; ++it) {
        int idx = it * 256 + tid;           // float4 index, 64*32
        int r   = idx >> 5;
        int c4  = (idx & 31) << 2;
        float4 v = *(const float4*)(Q + base + (size_t)(qt * 64 + r) * HIDDEN + c4);
        v.x *= scale; v.y *= scale; v.z *= scale; v.w *= scale;
        *(float4*)&Qs[r * 128 + c4] = v;
    }

    ull   O2[4][8];
    float m_i[4], l_i[4];
#pragma unroll
    for (int i = 0; i < 4; ++i) {
        m_i[i] = -3.402823466e38f;
        l_i[i] = 0.f;
#pragma unroll
        for (int j = 0; j < 8; ++j) O2[i][j] = 0ull;
    }

    for (int kt = 0; kt < SEQ / 64; ++kt) {
        __syncthreads();   // Q ready (1st iter) / previous tile fully consumed
        const float* Kg = K + base + (size_t)(kt * 64) * HIDDEN;
        const float* Vg = V + base + (size_t)(kt * 64) * HIDDEN;
#pragma unroll
        for (int it = 0; it < 16; ++it) {
            int idx = it * 256 + tid;       // float2 index, 64*64
            int r   = idx >> 6;             // kv row
            int c2  = idx & 63;             // d pair
            float2 kv = *(const float2*)(Kg + (size_t)r * HIDDEN + c2 * 2);
            *(float2*)&Kt[r * 130 + c2 * 2] = kv;
            float2 vv = *(const float2*)(Vg + (size_t)r * HIDDEN + c2 * 2);
            Vt[(c2 * 2    ) * 66 + r] = vv.x;
            Vt[(c2 * 2 + 1) * 66 + r] = vv.y;
        }
        __syncthreads();

        // ---- scores: pair-accumulate over d ----
        ull s2[4][4];
#pragma unroll
        for (int i = 0; i < 4; ++i)
#pragma unroll
            for (int j = 0; j < 4; ++j) s2[i][j] = 0ull;

#pragma unroll 2
        for (int d2 = 0; d2 < 64; ++d2) {
            ull q2[4], k2[4];
#pragma unroll
            for (int i = 0; i < 4; ++i)
                q2[i] = *(const ull*)&Qs[(ty * 4 + i) * 128 + d2 * 2];
#pragma unroll
            for (int j = 0; j < 4; ++j)
                k2[j] = *(const ull*)&Kt[(tx + 16 * j) * 130 + d2 * 2];
#pragma unroll
            for (int i = 0; i < 4; ++i)
#pragma unroll
                for (int j = 0; j < 4; ++j)
                    s2[i][j] = ffma2(q2[i], k2[j], s2[i][j]);
        }

        // ---- online softmax ----
#pragma unroll
        for (int i = 0; i < 4; ++i) {
            float s[4];
            float rmax = -3.402823466e38f;
#pragma unroll
            for (int j = 0; j < 4; ++j) {
                float2 f = funpack2(s2[i][j]);
                s[j] = f.x + f.y;
                rmax = fmaxf(rmax, s[j]);
            }
#pragma unroll
            for (int off = 8; off; off >>= 1)
                rmax = fmaxf(rmax, __shfl_xor_sync(0xffffffffu, rmax, off));
            float mnew = fmaxf(m_i[i], rmax);
            float c = __expf(m_i[i] - mnew);
            m_i[i] = mnew;
            float rsum = 0.f;
#pragma unroll
            for (int j = 0; j < 4; ++j) {
                float p = __expf(s[j] - mnew);
                rsum += p;
                Ps[(ty * 4 + i) * 80 + tx + 16 * j] = p;
            }
#pragma unroll
            for (int off = 8; off; off >>= 1)
                rsum += __shfl_xor_sync(0xffffffffu, rsum, off);
            l_i[i] = l_i[i] * c + rsum;
            ull cd = fdup2(c);
#pragma unroll
            for (int j = 0; j < 8; ++j) O2[i][j] = fmul2_(O2[i][j], cd);
        }
        __syncthreads();   // Ps visible to all tx

        // ---- O += P @ V : pair-accumulate over kv ----
#pragma unroll 2
        for (int kk = 0; kk < 32; ++kk) {
            ull p2[4], v2[8];
#pragma unroll
            for (int i = 0; i < 4; ++i)
                p2[i] = *(const ull*)&Ps[(ty * 4 + i) * 80 + kk * 2];
#pragma unroll
            for (int j = 0; j < 8; ++j)
                v2[j] = *(const ull*)&Vt[(tx + 16 * j) * 66 + kk * 2];
#pragma unroll
            for (int i = 0; i < 4; ++i)
#pragma unroll
                for (int j = 0; j < 8; ++j)
                    O2[i][j] = ffma2(p2[i], v2[j], O2[i][j]);
        }
    }

    // ---- epilogue: fold pairs, normalize ----
#pragma unroll
    for (int i = 0; i < 4; ++i) {
        float inv = 1.0f / l_i[i];
        size_t row = base + (size_t)(qt * 64 + ty * 4 + i) * HIDDEN;
#pragma unroll
        for (int j = 0; j < 8; ++j) {
            float2 f = funpack2(O2[i][j]);
            O[row + tx + 16 * j] = (f.x + f.y) * inv;
        }
    }
}

// =====================================================================
extern "C" void kernel_launch(void* const* d_in, const int* in_sizes, int n_in,
                              void* d_out, int out_size)
{
    const float* x  = (const float*)d_in[0];
    const float* wq = (const float*)d_in[1];
    const float* wk = (const float*)d_in[2];
    const float* wv = (const float*)d_in[3];
    const float* wo = (const float*)d_in[4];
    float* out = (float*)d_out;

    float *Qp, *Kp, *Vp, *Op;
    cudaGetSymbolAddress((void**)&Qp, g_Q);
    cudaGetSymbolAddress((void**)&Kp, g_K);
    cudaGetSymbolAddress((void**)&Vp, g_V);
    cudaGetSymbolAddress((void**)&Op, g_O);

    const int M = BATCH * SEQ;   // 4096
    dim3 ggrid(HIDDEN / 128, M / 128);   // (16, 32)

    sgemm_nt<<<ggrid, 256>>>(x, wq, Qp, M, HIDDEN, HIDDEN);
    sgemm_nt<<<ggrid, 256>>>(x, wk, Kp, M, HIDDEN, HIDDEN);
    sgemm_nt<<<ggrid, 256>>>(x, wv, Vp, M, HIDDEN, HIDDEN);

    cudaFuncSetAttribute(attn_kernel, cudaFuncAttributeMaxDynamicSharedMemorySize,
                         ATTN_SMEM_BYTES);
    attn_kernel<<<dim3(BATCH * NHEADS, SEQ / 64), 256, ATTN_SMEM_BYTES>>>(Qp, Kp, Vp, Op);

    sgemm_nt<<<ggrid, 256>>>(Op, wo, out, M, HIDDEN, HIDDEN);
}

// round 3
// speedup vs baseline: 1.5905x; 1.5905x over previous
#include <cuda_runtime.h>
#include <cuda_bf16.h>
#include <cstdint>

#define HIDDEN 2048
#define SEQ    2048
#define BATCH  2
#define NHEADS 16
#define HDIM   128
#define MROWS  (BATCH * SEQ)   // 4096

typedef unsigned long long ull;

// ---------- f32x2 packed-math helpers (sm_100+/sm_103a, non-gated) ----------
__device__ __forceinline__ ull fpack2(float lo, float hi) {
    ull r; asm("mov.b64 %0, {%1,%2};" : "=l"(r) : "f"(lo), "f"(hi)); return r;
}
__device__ __forceinline__ ull fdup2(float v) { return fpack2(v, v); }
__device__ __forceinline__ float2 funpack2(ull v) {
    float2 r; asm("mov.b64 {%0,%1}, %2;" : "=f"(r.x), "=f"(r.y) : "l"(v)); return r;
}
__device__ __forceinline__ ull ffma2(ull a, ull b, ull c) {
    ull d; asm("fma.rn.f32x2 %0, %1, %2, %3;" : "=l"(d) : "l"(a), "l"(b), "l"(c)); return d;
}
__device__ __forceinline__ ull fmul2_(ull a, ull b) {
    ull d; asm("mul.rn.f32x2 %0, %1, %2;" : "=l"(d) : "l"(a), "l"(b)); return d;
}

// ---------- scratch (no cudaMalloc allowed) ----------
__device__ float g_Q[MROWS * HIDDEN];
__device__ float g_K[MROWS * HIDDEN];
__device__ float g_V[MROWS * HIDDEN];
__device__ float g_O[MROWS * HIDDEN];
__device__ __nv_bfloat16 g_xh[MROWS * HIDDEN], g_xl[MROWS * HIDDEN];
__device__ __nv_bfloat16 g_oh[MROWS * HIDDEN], g_ol[MROWS * HIDDEN];
__device__ __nv_bfloat16 g_wqh[HIDDEN * HIDDEN], g_wql[HIDDEN * HIDDEN];
__device__ __nv_bfloat16 g_wkh[HIDDEN * HIDDEN], g_wkl[HIDDEN * HIDDEN];
__device__ __nv_bfloat16 g_wvh[HIDDEN * HIDDEN], g_wvl[HIDDEN * HIDDEN];
__device__ __nv_bfloat16 g_woh[HIDDEN * HIDDEN], g_wol[HIDDEN * HIDDEN];

// ---------- PTX wrappers (all sm_80-era, valid on compute_103) ----------
__device__ __forceinline__ uint32_t smem_u32(const void* p) {
    uint32_t a;
    asm("{ .reg .u64 t; cvta.to.shared.u64 t, %1; cvt.u32.u64 %0, t; }" : "=r"(a) : "l"(p));
    return a;
}
__device__ __forceinline__ void cp16(uint32_t sdst, const void* gsrc) {
    asm volatile("cp.async.cg.shared.global [%0], [%1], 16;" :: "r"(sdst), "l"(gsrc) : "memory");
}
#define CP_COMMIT() asm volatile("cp.async.commit_group;" ::: "memory")
#define CP_WAIT1()  asm volatile("cp.async.wait_group 1;" ::: "memory")

__device__ __forceinline__ void ldsm_x4(uint32_t (&r)[4], uint32_t addr) {
    asm volatile("ldmatrix.sync.aligned.m8n8.x4.shared.b16 {%0,%1,%2,%3}, [%4];"
                 : "=r"(r[0]), "=r"(r[1]), "=r"(r[2]), "=r"(r[3]) : "r"(addr));
}
__device__ __forceinline__ void mma16816(float (&d)[4], const uint32_t (&a)[4],
                                         uint32_t b0, uint32_t b1) {
    asm volatile(
        "mma.sync.aligned.m16n8k16.row.col.f32.bf16.bf16.f32 "
        "{%0,%1,%2,%3}, {%4,%5,%6,%7}, {%8,%9}, {%0,%1,%2,%3};"
        : "+f"(d[0]), "+f"(d[1]), "+f"(d[2]), "+f"(d[3])
        : "r"(a[0]), "r"(a[1]), "r"(a[2]), "r"(a[3]), "r"(b0), "r"(b1));
}

// ---------- fp32 -> bf16 hi/lo split ----------
__global__ __launch_bounds__(256)
void cvt_hilo(const float4* __restrict__ in, __nv_bfloat162* __restrict__ hi,
              __nv_bfloat162* __restrict__ lo, int n4)
{
    int i = blockIdx.x * blockDim.x + threadIdx.x;
    if (i >= n4) return;
    float4 v = in[i];
    __nv_bfloat16 hx = __float2bfloat16(v.x);
    __nv_bfloat16 hy = __float2bfloat16(v.y);
    __nv_bfloat16 hz = __float2bfloat16(v.z);
    __nv_bfloat16 hw = __float2bfloat16(v.w);
    hi[2 * i]     = __halves2bfloat162(hx, hy);
    hi[2 * i + 1] = __halves2bfloat162(hz, hw);
    __nv_bfloat16 lx = __float2bfloat16(v.x - __bfloat162float(hx));
    __nv_bfloat16 ly = __float2bfloat16(v.y - __bfloat162float(hy));
    __nv_bfloat16 lz = __float2bfloat16(v.z - __bfloat162float(hz));
    __nv_bfloat16 lw = __float2bfloat16(v.w - __bfloat162float(hw));
    lo[2 * i]     = __halves2bfloat162(lx, ly);
    lo[2 * i + 1] = __halves2bfloat162(lz, lw);
}

// =====================================================================
// HMMA GEMM: C[M,N] = (Ah+Al)[M,K] @ (Bh+Bl)[N,K]^T, fp32 accum in regs.
// 128x128 CTA tile, 8 warps (4m x 2n), warp tile 32x64, BK=64 bf16.
// 3-stage cp.async pipeline; XOR swizzle (seg ^ row&7) on 128B rows.
// Products: AhBh + AhBl + AlBh (lo*lo dropped, ~2^-16 rel).
// =====================================================================
#define BK        64
#define NK        (HIDDEN / BK)            // 32
#define TILE_B    16384                    // 128 rows * 128B
#define STAGE_B   (4 * TILE_B)             // Ah Al Bh Bl
#define GEMM_SMEM (3 * STAGE_B)            // 196608

__global__ __launch_bounds__(256, 1)
void gemm_mma(const __nv_bfloat16* __restrict__ Ah, const __nv_bfloat16* __restrict__ Al,
              const __nv_bfloat16* __restrict__ Bh, const __nv_bfloat16* __restrict__ Bl,
              float* __restrict__ C, int M, int N, int K)
{
    extern __shared__ __align__(128) char smem[];
    const uint32_t sbase = smem_u32(smem);
    const int tid  = threadIdx.x;
    const int wid  = tid >> 5;
    const int lane = tid & 31;
    const int wm   = wid & 3;          // m: 0..3 -> 32-row slab
    const int wn   = wid >> 2;         // n: 0..1 -> 64-col slab
    const size_t brow = (size_t)blockIdx.y * 128;
    const size_t bcol = (size_t)blockIdx.x * 128;

    // ---- cp.async slots: row = tid>>1, 4 x 16B segs each ----
    const int row  = tid >> 1;
    const int segq = (tid & 1) * 4;
    uint32_t swoff[4];
#pragma unroll
    for (int i = 0; i < 4; ++i)
        swoff[i] = (uint32_t)(row * 128 + (((segq + i) ^ (row & 7)) << 4));

    const size_t Kb = (size_t)K * 2;
    const char* pAh = (const char*)Ah + (brow + row) * Kb;
    const char* pAl = (const char*)Al + (brow + row) * Kb;
    const char* pBh = (const char*)Bh + (bcol + row) * Kb;
    const char* pBl = (const char*)Bl + (bcol + row) * Kb;

#define LOAD_CHUNK(c, s) do {                                             \
        uint32_t sb_ = sbase + (s) * STAGE_B;                             \
        size_t off_ = (size_t)(c) * 128;                                  \
        _Pragma("unroll")                                                 \
        for (int i_ = 0; i_ < 4; ++i_) {                                  \
            size_t g_ = off_ + (size_t)(((segq + i_)) << 4);              \
            cp16(sb_ + 0 * TILE_B + swoff[i_], pAh + g_);                 \
            cp16(sb_ + 1 * TILE_B + swoff[i_], pAl + g_);                 \
            cp16(sb_ + 2 * TILE_B + swoff[i_], pBh + g_);                 \
            cp16(sb_ + 3 * TILE_B + swoff[i_], pBl + g_);                 \
        }                                                                 \
    } while (0)

    // ---- ldmatrix per-lane row/seg components ----
    // A: lanes 0-15 -> rows m..m+15 (matrices 0,1); lanes 16-31 same rows, k+8
    const int rA = wm * 32 + (lane & 15);          // + mt*16
    const int aHalf = lane >> 4;                   // seg offset 0/1
    // B: lanes 0-7 -> n rows, k0; 8-15 -> same n rows, k+8; 16-31 -> n+8
    const int rB = wn * 64 + ((lane >> 4) << 3) + (lane & 7);   // + np*16
    const int bHalf = (lane >> 3) & 1;

    float acc[2][8][4];
#pragma unroll
    for (int mt = 0; mt < 2; ++mt)
#pragma unroll
        for (int nt = 0; nt < 8; ++nt)
#pragma unroll
            for (int q = 0; q < 4; ++q) acc[mt][nt][q] = 0.f;

    LOAD_CHUNK(0, 0); CP_COMMIT();
    LOAD_CHUNK(1, 1); CP_COMMIT();

    for (int c = 0; c < NK; ++c) {
        CP_WAIT1();           // chunk c's data complete (this thread)
        __syncthreads();      // all threads' data visible; all done with c-1

        if (c + 2 < NK) LOAD_CHUNK(c + 2, (c + 2) % 3);
        CP_COMMIT();          // unconditional: keeps group counting aligned

        const uint32_t sb = sbase + (uint32_t)(c % 3) * STAGE_B;

#pragma unroll
        for (int k16 = 0; k16 < 4; ++k16) {
            // ---- A fragments (hi & lo) ----
            uint32_t ah[2][4], al[2][4];
#pragma unroll
            for (int mt = 0; mt < 2; ++mt) {
                int r = rA + mt * 16;
                uint32_t seg = (uint32_t)((2 * k16 + aHalf) ^ (r & 7));
                uint32_t byteoff = (uint32_t)(r * 128) + (seg << 4);
                ldsm_x4(ah[mt], sb + 0 * TILE_B + byteoff);
                ldsm_x4(al[mt], sb + 1 * TILE_B + byteoff);
            }
            // ---- B fragments, 2 n8-tiles per ldmatrix.x4 ----
#pragma unroll
            for (int np = 0; np < 4; ++np) {
                int r = rB + np * 16;
                uint32_t seg = (uint32_t)((2 * k16 + bHalf) ^ (r & 7));
                uint32_t byteoff = (uint32_t)(r * 128) + (seg << 4);
                uint32_t bh[4], bl[4];
                ldsm_x4(bh, sb + 2 * TILE_B + byteoff);
                ldsm_x4(bl, sb + 3 * TILE_B + byteoff);
#pragma unroll
                for (int mt = 0; mt < 2; ++mt) {
                    mma16816(acc[mt][2 * np + 0], ah[mt], bh[0], bh[1]);
                    mma16816(acc[mt][2 * np + 1], ah[mt], bh[2], bh[3]);
                    mma16816(acc[mt][2 * np + 0], al[mt], bh[0], bh[1]);
                    mma16816(acc[mt][2 * np + 1], al[mt], bh[2], bh[3]);
                    mma16816(acc[mt][2 * np + 0], ah[mt], bl[0], bl[1]);
                    mma16816(acc[mt][2 * np + 1], ah[mt], bl[2], bl[3]);
                }
            }
        }
    }

    // ---- epilogue: direct fp32 stores ----
#pragma unroll
    for (int mt = 0; mt < 2; ++mt) {
        size_t r0 = brow + wm * 32 + mt * 16 + (lane >> 2);
#pragma unroll
        for (int nt = 0; nt < 8; ++nt) {
            size_t col = bcol + wn * 64 + nt * 8 + 2 * (lane & 3);
            *(float2*)&C[r0 * (size_t)N + col]       = make_float2(acc[mt][nt][0], acc[mt][nt][1]);
            *(float2*)&C[(r0 + 8) * (size_t)N + col] = make_float2(acc[mt][nt][2], acc[mt][nt][3]);
        }
    }
}

// =====================================================================
// Flash attention (non-causal), fp32, f32x2 packed inner loops (unchanged).
// =====================================================================
#define ATTN_SMEM_FLOATS (8192 + 8320 + 8448 + 5120)
#define ATTN_SMEM_BYTES  (ATTN_SMEM_FLOATS * 4)

__global__ __launch_bounds__(256, 1)
void attn_kernel(const float* __restrict__ Q, const float* __restrict__ K,
                 const float* __restrict__ V, float* __restrict__ O)
{
    extern __shared__ __align__(16) float sm[];
    float* Qs = sm;                 // [64][128]
    float* Kt = sm + 8192;          // [64][130]
    float* Vt = sm + 16512;         // [128][66]
    float* Ps = sm + 24960;         // [64][80]

    const int tid = threadIdx.x;
    const int tx  = tid & 15;
    const int ty  = tid >> 4;
    const int b   = blockIdx.x >> 4;
    const int h   = blockIdx.x & 15;
    const int qt  = blockIdx.y;

    const float scale = 0.08838834764831843f;
    const size_t base = ((size_t)b * SEQ) * HIDDEN + (size_t)h * HDIM;

#pragma unroll
    for (int it = 0; it < 8; ++it) {
        int idx = it * 256 + tid;
        int r   = idx >> 5;
        int c4  = (idx & 31) << 2;
        float4 v = *(const float4*)(Q + base + (size_t)(qt * 64 + r) * HIDDEN + c4);
        v.x *= scale; v.y *= scale; v.z *= scale; v.w *= scale;
        *(float4*)&Qs[r * 128 + c4] = v;
    }

    ull   O2[4][8];
    float m_i[4], l_i[4];
#pragma unroll
    for (int i = 0; i < 4; ++i) {
        m_i[i] = -3.402823466e38f;
        l_i[i] = 0.f;
#pragma unroll
        for (int j = 0; j < 8; ++j) O2[i][j] = 0ull;
    }

    for (int kt = 0; kt < SEQ / 64; ++kt) {
        __syncthreads();
        const float* Kg = K + base + (size_t)(kt * 64) * HIDDEN;
        const float* Vg = V + base + (size_t)(kt * 64) * HIDDEN;
#pragma unroll
        for (int it = 0; it < 16; ++it) {
            int idx = it * 256 + tid;
            int r   = idx >> 6;
            int c2  = idx & 63;
            float2 kv = *(const float2*)(Kg + (size_t)r * HIDDEN + c2 * 2);
            *(float2*)&Kt[r * 130 + c2 * 2] = kv;
            float2 vv = *(const float2*)(Vg + (size_t)r * HIDDEN + c2 * 2);
            Vt[(c2 * 2    ) * 66 + r] = vv.x;
            Vt[(c2 * 2 + 1) * 66 + r] = vv.y;
        }
        __syncthreads();

        ull s2[4][4];
#pragma unroll
        for (int i = 0; i < 4; ++i)
#pragma unroll
            for (int j = 0; j < 4; ++j) s2[i][j] = 0ull;

#pragma unroll 2
        for (int d2 = 0; d2 < 64; ++d2) {
            ull q2[4], k2[4];
#pragma unroll
            for (int i = 0; i < 4; ++i)
                q2[i] = *(const ull*)&Qs[(ty * 4 + i) * 128 + d2 * 2];
#pragma unroll
            for (int j = 0; j < 4; ++j)
                k2[j] = *(const ull*)&Kt[(tx + 16 * j) * 130 + d2 * 2];
#pragma unroll
            for (int i = 0; i < 4; ++i)
#pragma unroll
                for (int j = 0; j < 4; ++j)
                    s2[i][j] = ffma2(q2[i], k2[j], s2[i][j]);
        }

#pragma unroll
        for (int i = 0; i < 4; ++i) {
            float s[4];
            float rmax = -3.402823466e38f;
#pragma unroll
            for (int j = 0; j < 4; ++j) {
                float2 f = funpack2(s2[i][j]);
                s[j] = f.x + f.y;
                rmax = fmaxf(rmax, s[j]);
            }
#pragma unroll
            for (int off = 8; off; off >>= 1)
                rmax = fmaxf(rmax, __shfl_xor_sync(0xffffffffu, rmax, off));
            float mnew = fmaxf(m_i[i], rmax);
            float c = __expf(m_i[i] - mnew);
            m_i[i] = mnew;
            float rsum = 0.f;
#pragma unroll
            for (int j = 0; j < 4; ++j) {
                float p = __expf(s[j] - mnew);
                rsum += p;
                Ps[(ty * 4 + i) * 80 + tx + 16 * j] = p;
            }
#pragma unroll
            for (int off = 8; off; off >>= 1)
                rsum += __shfl_xor_sync(0xffffffffu, rsum, off);
            l_i[i] = l_i[i] * c + rsum;
            ull cd = fdup2(c);
#pragma unroll
            for (int j = 0; j < 8; ++j) O2[i][j] = fmul2_(O2[i][j], cd);
        }
        __syncthreads();

#pragma unroll 2
        for (int kk = 0; kk < 32; ++kk) {
            ull p2[4], v2[8];
#pragma unroll
            for (int i = 0; i < 4; ++i)
                p2[i] = *(const ull*)&Ps[(ty * 4 + i) * 80 + kk * 2];
#pragma unroll
            for (int j = 0; j < 8; ++j)
                v2[j] = *(const ull*)&Vt[(tx + 16 * j) * 66 + kk * 2];
#pragma unroll
            for (int i = 0; i < 4; ++i)
#pragma unroll
                for (int j = 0; j < 8; ++j)
                    O2[i][j] = ffma2(p2[i], v2[j], O2[i][j]);
        }
    }

#pragma unroll
    for (int i = 0; i < 4; ++i) {
        float inv = 1.0f / l_i[i];
        size_t row = base + (size_t)(qt * 64 + ty * 4 + i) * HIDDEN;
#pragma unroll
        for (int j = 0; j < 8; ++j) {
            float2 f = funpack2(O2[i][j]);
            O[row + tx + 16 * j] = (f.x + f.y) * inv;
        }
    }
}

// =====================================================================
extern "C" void kernel_launch(void* const* d_in, const int* in_sizes, int n_in,
                              void* d_out, int out_size)
{
    const float* x  = (const float*)d_in[0];
    const float* wq = (const float*)d_in[1];
    const float* wk = (const float*)d_in[2];
    const float* wv = (const float*)d_in[3];
    const float* wo = (const float*)d_in[4];
    float* out = (float*)d_out;

    float *Qp, *Kp, *Vp, *Op;
    cudaGetSymbolAddress((void**)&Qp, g_Q);
    cudaGetSymbolAddress((void**)&Kp, g_K);
    cudaGetSymbolAddress((void**)&Vp, g_V);
    cudaGetSymbolAddress((void**)&Op, g_O);
    __nv_bfloat16 *xh, *xl, *oh, *ol;
    __nv_bfloat16 *wqh, *wql, *wkh, *wkl, *wvh, *wvl, *woh, *wol;
    cudaGetSymbolAddress((void**)&xh, g_xh);  cudaGetSymbolAddress((void**)&xl, g_xl);
    cudaGetSymbolAddress((void**)&oh, g_oh);  cudaGetSymbolAddress((void**)&ol, g_ol);
    cudaGetSymbolAddress((void**)&wqh, g_wqh); cudaGetSymbolAddress((void**)&wql, g_wql);
    cudaGetSymbolAddress((void**)&wkh, g_wkh); cudaGetSymbolAddress((void**)&wkl, g_wkl);
    cudaGetSymbolAddress((void**)&wvh, g_wvh); cudaGetSymbolAddress((void**)&wvl, g_wvl);
    cudaGetSymbolAddress((void**)&woh, g_woh); cudaGetSymbolAddress((void**)&wol, g_wol);

    const int M = MROWS;                    // 4096
    const int n4x = M * HIDDEN / 4;
    const int n4w = HIDDEN * HIDDEN / 4;

    cvt_hilo<<<n4x / 256, 256>>>((const float4*)x,  (__nv_bfloat162*)xh,  (__nv_bfloat162*)xl,  n4x);
    cvt_hilo<<<n4w / 256, 256>>>((const float4*)wq, (__nv_bfloat162*)wqh, (__nv_bfloat162*)wql, n4w);
    cvt_hilo<<<n4w / 256, 256>>>((const float4*)wk, (__nv_bfloat162*)wkh, (__nv_bfloat162*)wkl, n4w);
    cvt_hilo<<<n4w / 256, 256>>>((const float4*)wv, (__nv_bfloat162*)wvh, (__nv_bfloat162*)wvl, n4w);
    cvt_hilo<<<n4w / 256, 256>>>((const float4*)wo, (__nv_bfloat162*)woh, (__nv_bfloat162*)wol, n4w);

    cudaFuncSetAttribute(gemm_mma, cudaFuncAttributeMaxDynamicSharedMemorySize, GEMM_SMEM);
    dim3 ggrid(HIDDEN / 128, M / 128);      // (16, 32)
    gemm_mma<<<ggrid, 256, GEMM_SMEM>>>(xh, xl, wqh, wql, Qp, M, HIDDEN, HIDDEN);
    gemm_mma<<<ggrid, 256, GEMM_SMEM>>>(xh, xl, wkh, wkl, Kp, M, HIDDEN, HIDDEN);
    gemm_mma<<<ggrid, 256, GEMM_SMEM>>>(xh, xl, wvh, wvl, Vp, M, HIDDEN, HIDDEN);

    cudaFuncSetAttribute(attn_kernel, cudaFuncAttributeMaxDynamicSharedMemorySize,
                         ATTN_SMEM_BYTES);
    attn_kernel<<<dim3(BATCH * NHEADS, SEQ / 64), 256, ATTN_SMEM_BYTES>>>(Qp, Kp, Vp, Op);

    cvt_hilo<<<n4x / 256, 256>>>((const float4*)Op, (__nv_bfloat162*)oh, (__nv_bfloat162*)ol, n4x);
    gemm_mma<<<ggrid, 256, GEMM_SMEM>>>(oh, ol, woh, wol, out, M, HIDDEN, HIDDEN);
}